// round 2
// baseline (speedup 1.0000x reference)
#include <cuda_runtime.h>

#define F_EPS 1e-10f

// ---------------------------------------------------------------------------
// Uniform (batch-invariant) constants, derived per-block by thread 0.
// ---------------------------------------------------------------------------
struct Consts {
    float mu1_0, mu1_1, mu2_0, mu2_1;
    float S1a, S1b, S1c;      // Sigma1: [a b; b c]
    float S2a, S2b, S2c;      // Sigma2
    float phi00, phi01, phi10, phi11;
    float s00, s01, s11;      // spd_core = tril @ tril^T
    float omega, lam, r;
};

// Lambda / r arrive from Python ints -> may be int32 bits or float32 bits.
__device__ __forceinline__ float decode_scalar_bits(int bits) {
    if (bits == 0) return 0.0f;
    float fv = __int_as_float(bits);
    float af = fabsf(fv);
    if (af >= 1e-30f && af <= 1e30f) return fv;   // looks like a float
    return (float)bits;                            // it was an int
}

__device__ __forceinline__ void build_consts(Consts& c,
                                             const float* omega, const float* mu1,
                                             const float* mu2, const float* Sig1,
                                             const float* Sig2, const float* phi,
                                             const float* ctril, const int* Lambda,
                                             const int* r) {
    c.mu1_0 = mu1[0]; c.mu1_1 = mu1[1];
    c.mu2_0 = mu2[0]; c.mu2_1 = mu2[1];
    c.S1a = Sig1[0]; c.S1b = Sig1[1]; c.S1c = Sig1[3];
    c.S2a = Sig2[0]; c.S2b = Sig2[1]; c.S2c = Sig2[3];
    c.phi00 = phi[0]; c.phi01 = phi[1];
    c.phi10 = phi[2]; c.phi11 = phi[3];
    float C00 = ctril[0], C10 = ctril[2], C11 = ctril[3];
    float e0 = expf(C00), e1 = expf(C11);
    c.s00 = e0 * e0;
    c.s01 = e0 * C10;
    c.s11 = C10 * C10 + e1 * e1;
    c.omega = omega[0];
    c.lam = decode_scalar_bits(Lambda[0]);
    c.r   = decode_scalar_bits(r[0]);
}

// ---------------------------------------------------------------------------
// Per-element closed form (N=2). See R0 derivation.
// ---------------------------------------------------------------------------
__device__ __forceinline__ void compute_elem(const Consts& c,
                                             float xv, float pv, float dv, float fv,
                                             float& m0, float& m1, float4& cov) {
    float pm1 = 1.0f - pv;
    float em0 = fmaf(pv, c.mu1_0, pm1 * c.mu2_0) - c.r;
    float em1 = fmaf(pv, c.mu1_1, pm1 * c.mu2_1) - c.r;

    float a = fmaf(pv, c.S1a, pm1 * c.S2a) + F_EPS;
    float b = fmaf(pv, c.S1b, pm1 * c.S2b);
    float d = fmaf(pv, c.S1c, pm1 * c.S2c) + F_EPS;

    float inv_l11 = rsqrtf(a);
    float l21     = b * inv_l11;
    float t       = d - l21 * l21;
    float inv_l22 = rsqrtf(t);

    float adj = pv - dv * pv * pm1;
    float s0 = fmaf(c.phi00, adj, c.phi01) * em0;
    float s1 = fmaf(c.phi10, adj, c.phi11) * em1;

    float sti1 = s1 * inv_l22;
    float sti0 = (s0 - l21 * sti1) * inv_l11;

    float mx = -(xv - c.omega);
    m0 = mx * sti0;
    m1 = mx * sti1;

    float u00 = inv_l11;
    float u11 = inv_l22;
    float u01 = -l21 * inv_l11 * inv_l22;

    float M00 = u00 * u00 * c.s00 + 2.0f * u00 * u01 * c.s01 + u01 * u01 * c.s11;
    float M01 = u11 * fmaf(u00, c.s01, u01 * c.s11);
    float M11 = u11 * u11 * c.s11;

    float sc = 0.5f * c.lam * fv;
    cov.x = fmaf(sc, M00, F_EPS);
    cov.y = sc * M01;
    cov.z = sc * M01;
    cov.w = fmaf(sc, M11, F_EPS);
}

#define ELEMS_PER_THREAD 8

__global__ void __launch_bounds__(256)
poemv_kernel(const float* __restrict__ x, const float* __restrict__ p,
             const float* __restrict__ dlnf, const float* __restrict__ f,
             float* __restrict__ out_mean, float* __restrict__ out_cov, int B,
             const float* __restrict__ omega, const float* __restrict__ mu1,
             const float* __restrict__ mu2, const float* __restrict__ S1,
             const float* __restrict__ S2, const float* __restrict__ phi,
             const float* __restrict__ ct, const int* __restrict__ Lam,
             const int* __restrict__ rr) {
    __shared__ Consts sc;
    if (threadIdx.x == 0) {
        build_consts(sc, omega, mu1, mu2, S1, S2, phi, ct, Lam, rr);
    }
    __syncthreads();
    const Consts c = sc;

    int t = blockIdx.x * blockDim.x + threadIdx.x;
    int i0 = t * ELEMS_PER_THREAD;

    if (i0 + ELEMS_PER_THREAD - 1 < B) {
        // Front-batched loads: 8 independent LDG.128 in flight (MLP=8).
        float4 xv0 = __ldcs((const float4*)(x + i0));
        float4 xv1 = __ldcs((const float4*)(x + i0 + 4));
        float4 pv0 = __ldcs((const float4*)(p + i0));
        float4 pv1 = __ldcs((const float4*)(p + i0 + 4));
        float4 dv0 = __ldcs((const float4*)(dlnf + i0));
        float4 dv1 = __ldcs((const float4*)(dlnf + i0 + 4));
        float4 fv0 = __ldcs((const float4*)(f + i0));
        float4 fv1 = __ldcs((const float4*)(f + i0 + 4));

        float m[16];
        float4 cv[8];
        compute_elem(c, xv0.x, pv0.x, dv0.x, fv0.x, m[0],  m[1],  cv[0]);
        compute_elem(c, xv0.y, pv0.y, dv0.y, fv0.y, m[2],  m[3],  cv[1]);
        compute_elem(c, xv0.z, pv0.z, dv0.z, fv0.z, m[4],  m[5],  cv[2]);
        compute_elem(c, xv0.w, pv0.w, dv0.w, fv0.w, m[6],  m[7],  cv[3]);
        compute_elem(c, xv1.x, pv1.x, dv1.x, fv1.x, m[8],  m[9],  cv[4]);
        compute_elem(c, xv1.y, pv1.y, dv1.y, fv1.y, m[10], m[11], cv[5]);
        compute_elem(c, xv1.z, pv1.z, dv1.z, fv1.z, m[12], m[13], cv[6]);
        compute_elem(c, xv1.w, pv1.w, dv1.w, fv1.w, m[14], m[15], cv[7]);

        // mean: 16 consecutive floats -> 4x 128-bit streaming stores
        float4* mb = (float4*)(out_mean + (size_t)2 * i0);
        __stcs(mb + 0, make_float4(m[0],  m[1],  m[2],  m[3]));
        __stcs(mb + 1, make_float4(m[4],  m[5],  m[6],  m[7]));
        __stcs(mb + 2, make_float4(m[8],  m[9],  m[10], m[11]));
        __stcs(mb + 3, make_float4(m[12], m[13], m[14], m[15]));
        // cov: 8x 128-bit streaming stores
        float4* cb = (float4*)(out_cov + (size_t)4 * i0);
        #pragma unroll
        for (int k = 0; k < 8; k++) __stcs(cb + k, cv[k]);
    } else {
        for (int k = 0; k < ELEMS_PER_THREAD; k++) {
            int i = i0 + k;
            if (i < B) {
                float m0, m1; float4 cvv;
                compute_elem(c, x[i], p[i], dlnf[i], f[i], m0, m1, cvv);
                out_mean[(size_t)2 * i]     = m0;
                out_mean[(size_t)2 * i + 1] = m1;
                float* cb = out_cov + (size_t)4 * i;
                cb[0] = cvv.x; cb[1] = cvv.y; cb[2] = cvv.z; cb[3] = cvv.w;
            }
        }
    }
}

extern "C" void kernel_launch(void* const* d_in, const int* in_sizes, int n_in,
                              void* d_out, int out_size) {
    const float* x     = (const float*)d_in[0];
    const float* omega = (const float*)d_in[1];
    const float* p     = (const float*)d_in[2];
    const float* dlnf  = (const float*)d_in[3];
    const float* f     = (const float*)d_in[4];
    const float* mu1   = (const float*)d_in[5];
    const float* mu2   = (const float*)d_in[6];
    const float* S1    = (const float*)d_in[7];
    const float* S2    = (const float*)d_in[8];
    const float* phi   = (const float*)d_in[9];
    const float* ct    = (const float*)d_in[10];
    const int*   Lam   = (const int*)d_in[11];
    const int*   r     = (const int*)d_in[12];

    int B = in_sizes[0];
    float* out      = (float*)d_out;
    float* out_mean = out;                       // (B, 2) flattened
    float* out_cov  = out + (size_t)B * 2;       // (B, 2, 2) flattened

    const int threads = 256;
    const int per_block = threads * ELEMS_PER_THREAD;
    int grid = (B + per_block - 1) / per_block;
    poemv_kernel<<<grid, threads>>>(x, p, dlnf, f, out_mean, out_cov, B,
                                    omega, mu1, mu2, S1, S2, phi, ct, Lam, r);
}

// round 3
// speedup vs baseline: 1.1879x; 1.1879x over previous
#include <cuda_runtime.h>

#define F_EPS 1e-10f

// ---------------------------------------------------------------------------
// Uniform (batch-invariant) constants, built per-thread from vectorized
// uniform loads (all warps hit the same L1/L2 lines -> broadcast).
// ---------------------------------------------------------------------------
struct Consts {
    float mu1_0, mu1_1, mu2_0, mu2_1;
    float S1a, S1b, S1c;      // Sigma1: [a b; b c]
    float S2a, S2b, S2c;      // Sigma2
    float phi00, phi01, phi10, phi11;
    float s00, s01, s11;      // spd_core = tril @ tril^T
    float omega, lam, r;
};

// Lambda / r arrive from Python ints -> may be int32 bits or float32 bits.
__device__ __forceinline__ float decode_scalar_bits(int bits) {
    if (bits == 0) return 0.0f;
    float fv = __int_as_float(bits);
    float af = fabsf(fv);
    if (af >= 1e-30f && af <= 1e30f) return fv;   // looks like a float
    return (float)bits;                            // it was an int
}

__device__ __forceinline__ Consts build_consts(const float* __restrict__ omega,
                                               const float* __restrict__ mu1,
                                               const float* __restrict__ mu2,
                                               const float* __restrict__ Sig1,
                                               const float* __restrict__ Sig2,
                                               const float* __restrict__ phi,
                                               const float* __restrict__ ctril,
                                               const int* __restrict__ Lambda,
                                               const int* __restrict__ r) {
    Consts c;
    // Vectorized uniform loads: 4x float4 + 2x float2 + 3 scalars = 9 LDG.
    float4 s1 = __ldg((const float4*)Sig1);   // [a b; b c] row-major
    float4 s2 = __ldg((const float4*)Sig2);
    float4 ph = __ldg((const float4*)phi);    // phi[0,0] phi[0,1] phi[1,0] phi[1,1]
    float4 ctv = __ldg((const float4*)ctril);
    float2 m1 = __ldg((const float2*)mu1);
    float2 m2 = __ldg((const float2*)mu2);

    c.mu1_0 = m1.x; c.mu1_1 = m1.y;
    c.mu2_0 = m2.x; c.mu2_1 = m2.y;
    c.S1a = s1.x; c.S1b = s1.y; c.S1c = s1.w;
    c.S2a = s2.x; c.S2b = s2.y; c.S2c = s2.w;
    c.phi00 = ph.x; c.phi01 = ph.y;
    c.phi10 = ph.z; c.phi11 = ph.w;
    // tril T = [[exp(C00), 0], [C10, exp(C11)]];  S = T T^T
    float C00 = ctv.x, C10 = ctv.z, C11 = ctv.w;
    float e0 = expf(C00), e1 = expf(C11);
    c.s00 = e0 * e0;
    c.s01 = e0 * C10;
    c.s11 = C10 * C10 + e1 * e1;
    c.omega = __ldg(omega);
    c.lam = decode_scalar_bits(__ldg(Lambda));
    c.r   = decode_scalar_bits(__ldg(r));
    return c;
}

// ---------------------------------------------------------------------------
// Per-element closed form (N=2):
//   Sigma_bar = p*S1 + (1-p)*S2 + EPS*I = [a b; b c]
//   chol: inv_l11 = rsqrt(a), l21 = b*inv_l11, inv_l22 = rsqrt(d - l21^2)
//   adj = p - dlnf_dp*p*(1-p);  signal_j = (phi[j,0]*adj + phi[j,1])*excess_mu_j
//   solve U x = s:  x1 = s1*inv_l22;  x0 = (s0 - l21*x1)*inv_l11
//   mean = -(x - omega) * x
//   inv_U = [[inv_l11, -l21*inv_l11*inv_l22], [0, inv_l22]]
//   cov = 0.5*lam*f * inv_U S inv_U^T + EPS*I
// ---------------------------------------------------------------------------
__device__ __forceinline__ void compute_elem(const Consts& c,
                                             float xv, float pv, float dv, float fv,
                                             float& m0, float& m1, float4& cov) {
    float pm1 = 1.0f - pv;
    float em0 = fmaf(pv, c.mu1_0, pm1 * c.mu2_0) - c.r;
    float em1 = fmaf(pv, c.mu1_1, pm1 * c.mu2_1) - c.r;

    float a = fmaf(pv, c.S1a, pm1 * c.S2a) + F_EPS;
    float b = fmaf(pv, c.S1b, pm1 * c.S2b);
    float d = fmaf(pv, c.S1c, pm1 * c.S2c) + F_EPS;

    float inv_l11 = rsqrtf(a);
    float l21     = b * inv_l11;
    float t       = d - l21 * l21;
    float inv_l22 = rsqrtf(t);

    float adj = pv - dv * pv * pm1;
    float s0 = fmaf(c.phi00, adj, c.phi01) * em0;
    float s1 = fmaf(c.phi10, adj, c.phi11) * em1;

    float sti1 = s1 * inv_l22;
    float sti0 = (s0 - l21 * sti1) * inv_l11;

    float mx = -(xv - c.omega);
    m0 = mx * sti0;
    m1 = mx * sti1;

    float u00 = inv_l11;
    float u11 = inv_l22;
    float u01 = -l21 * inv_l11 * inv_l22;

    float M00 = u00 * u00 * c.s00 + 2.0f * u00 * u01 * c.s01 + u01 * u01 * c.s11;
    float M01 = u11 * fmaf(u00, c.s01, u01 * c.s11);
    float M11 = u11 * u11 * c.s11;

    float sc = 0.5f * c.lam * fv;
    cov.x = fmaf(sc, M00, F_EPS);
    cov.y = sc * M01;
    cov.z = sc * M01;
    cov.w = fmaf(sc, M11, F_EPS);
}

__global__ void __launch_bounds__(256)
poemv_kernel(const float* __restrict__ x, const float* __restrict__ p,
             const float* __restrict__ dlnf, const float* __restrict__ f,
             float* __restrict__ out_mean, float* __restrict__ out_cov, int B,
             const float* __restrict__ omega, const float* __restrict__ mu1,
             const float* __restrict__ mu2, const float* __restrict__ S1,
             const float* __restrict__ S2, const float* __restrict__ phi,
             const float* __restrict__ ct, const int* __restrict__ Lam,
             const int* __restrict__ rr) {
    const Consts c = build_consts(omega, mu1, mu2, S1, S2, phi, ct, Lam, rr);

    int t = blockIdx.x * blockDim.x + threadIdx.x;
    int i0 = t * 4;

    if (i0 + 3 < B) {
        float4 xv = *(const float4*)(x + i0);
        float4 pv = *(const float4*)(p + i0);
        float4 dv = *(const float4*)(dlnf + i0);
        float4 fv = *(const float4*)(f + i0);

        float m[8];
        float4 cv[4];
        compute_elem(c, xv.x, pv.x, dv.x, fv.x, m[0], m[1], cv[0]);
        compute_elem(c, xv.y, pv.y, dv.y, fv.y, m[2], m[3], cv[1]);
        compute_elem(c, xv.z, pv.z, dv.z, fv.z, m[4], m[5], cv[2]);
        compute_elem(c, xv.w, pv.w, dv.w, fv.w, m[6], m[7], cv[3]);

        // mean: 8 consecutive floats -> two 128-bit stores
        *(float4*)(out_mean + (size_t)2 * i0)     = make_float4(m[0], m[1], m[2], m[3]);
        *(float4*)(out_mean + (size_t)2 * i0 + 4) = make_float4(m[4], m[5], m[6], m[7]);
        // cov: 4x 128-bit stores
        float4* cb = (float4*)(out_cov + (size_t)4 * i0);
        cb[0] = cv[0]; cb[1] = cv[1]; cb[2] = cv[2]; cb[3] = cv[3];
    } else {
        for (int k = 0; k < 4; k++) {
            int i = i0 + k;
            if (i < B) {
                float m0, m1; float4 cvv;
                compute_elem(c, x[i], p[i], dlnf[i], f[i], m0, m1, cvv);
                out_mean[(size_t)2 * i]     = m0;
                out_mean[(size_t)2 * i + 1] = m1;
                float* cb = out_cov + (size_t)4 * i;
                cb[0] = cvv.x; cb[1] = cvv.y; cb[2] = cvv.z; cb[3] = cvv.w;
            }
        }
    }
}

extern "C" void kernel_launch(void* const* d_in, const int* in_sizes, int n_in,
                              void* d_out, int out_size) {
    const float* x     = (const float*)d_in[0];
    const float* omega = (const float*)d_in[1];
    const float* p     = (const float*)d_in[2];
    const float* dlnf  = (const float*)d_in[3];
    const float* f     = (const float*)d_in[4];
    const float* mu1   = (const float*)d_in[5];
    const float* mu2   = (const float*)d_in[6];
    const float* S1    = (const float*)d_in[7];
    const float* S2    = (const float*)d_in[8];
    const float* phi   = (const float*)d_in[9];
    const float* ct    = (const float*)d_in[10];
    const int*   Lam   = (const int*)d_in[11];
    const int*   r     = (const int*)d_in[12];

    int B = in_sizes[0];
    float* out      = (float*)d_out;
    float* out_mean = out;                       // (B, 2) flattened
    float* out_cov  = out + (size_t)B * 2;       // (B, 2, 2) flattened

    const int threads = 256;
    int grid = (B + threads * 4 - 1) / (threads * 4);
    poemv_kernel<<<grid, threads>>>(x, p, dlnf, f, out_mean, out_cov, B,
                                    omega, mu1, mu2, S1, S2, phi, ct, Lam, r);
}